// round 9
// baseline (speedup 1.0000x reference)
#include <cuda_runtime.h>
#include <math.h>
#include <stdint.h>

#define Bb 2
#define Tt 1024
#define Dd 1024
#define Hh 8
#define DEPTH 5
#define NTOK (Bb*Tt)

// ---------------- scratch (device globals; allocation-free) ----------------
__device__ float g_paths[NTOK*Hh*DEPTH];      // [token][h*5+d]
__device__ float g_xr[NTOK*Dd];               // tf32(rna) hi part of x
__device__ float g_xlo[NTOK*Dd];              // tf32 lo residual of x
__device__ float g_wph[Dd*128];               // Wp hi, padded [k][128]
__device__ float g_wpl[Dd*128];               // Wp lo, padded [k][128]
__device__ float g_pp[4*NTOK*128];            // paths split-K partial logits
__device__ float g_wvr[Dd*Dd];                // rounded Wv [k][n]
__device__ float g_wor[Dd*Dd];                // rounded Wo [k][n]
__device__ float g_v[NTOK*Dd];                // V = x@Wv, rounded
__device__ float g_ctx[NTOK*Dd];              // ctx (t<512 final; t>=512 partial slot0)
__device__ float g_ctx2[NTOK*Dd];             // ctx partial slot1 (t>=512 only)
__device__ float g_rs[2*Bb*Hh*Tt];            // row sums [slot][bh][t] (t>=512 only used)

// av jobs (24/bh, longest first). qt<8 full (self-normalized); qt>=8 split.
__constant__ int c_qt[24] = {15,15,14,14,13,13,12,12,11,11,10,10, 9, 9, 8, 8, 7, 6, 5, 4, 3, 2, 1, 0};
__constant__ int c_k0[24] = { 0,16, 0,15, 0,14, 0,13, 0,12, 0,11, 0,10, 0, 9, 0, 0, 0, 0, 0, 0, 0, 0};
__constant__ int c_kt[24] = {16,16,15,15,14,14,13,13,12,12,11,11,10,10, 9, 9,16,14,12,10, 8, 6, 4, 2};
__constant__ int c_ds[24] = { 0, 1, 0, 1, 0, 1, 0, 1, 0, 1, 0, 1, 0, 1, 0, 1, 0, 0, 0, 0, 0, 0, 0, 0};

// ---------------- helpers ----------------
__device__ __forceinline__ float rnaf(float f) {
    uint32_t r; asm("cvt.rna.tf32.f32 %0, %1;" : "=r"(r) : "f"(f));
    return __uint_as_float(r);
}
__device__ __forceinline__ uint32_t smem_u32(const void* p) {
    uint32_t a;
    asm("{ .reg .u64 t; cvta.to.shared.u64 t, %1; cvt.u32.u64 %0, t; }" : "=r"(a) : "l"(p));
    return a;
}
__device__ __forceinline__ void cp16(uint32_t dst, const void* src) {
    asm volatile("cp.async.cg.shared.global [%0], [%1], 16;" :: "r"(dst), "l"(src));
}
__device__ __forceinline__ void mma_tf32(float c[4],
                                         uint32_t a0, uint32_t a1, uint32_t a2, uint32_t a3,
                                         uint32_t b0, uint32_t b1) {
    asm volatile("mma.sync.aligned.m16n8k8.row.col.f32.tf32.tf32.f32 "
                 "{%0,%1,%2,%3}, {%4,%5,%6,%7}, {%8,%9}, {%0,%1,%2,%3};"
                 : "+f"(c[0]), "+f"(c[1]), "+f"(c[2]), "+f"(c[3])
                 : "r"(a0), "r"(a1), "r"(a2), "r"(a3), "r"(b0), "r"(b1));
}
__device__ __forceinline__ float expap(float x) {   // e^x, x in (0,1], deg-7
    float p = 1.98412698e-4f;
    p = fmaf(p, x, 1.38888889e-3f);
    p = fmaf(p, x, 8.33333333e-3f);
    p = fmaf(p, x, 4.16666667e-2f);
    p = fmaf(p, x, 1.66666667e-1f);
    p = fmaf(p, x, 0.5f);
    p = fmaf(p, x, 1.0f);
    p = fmaf(p, x, 1.0f);
    return p;
}

#define ASTRIDE 36
#define BSTRIDE 136

// ---------------------------------------------------------------------------
// dense tf32 GEMM: C[128,128] tile, 512 threads = 16 warps (4m x 4n grid,
// warp tile 32x32), BK=32, 3-stage cp.async. 4 warps/SMSP for latency hiding.
// ---------------------------------------------------------------------------
#define A2FLOATS (128*ASTRIDE)                 // 4608
#define STAGEF2  (A2FLOATS + 32*BSTRIDE)       // 8960 floats
#define SMEM_GEMM2 (3*STAGEF2*4)               // 107520 B

__device__ __forceinline__ void load_stage512(uint32_t sb, int s,
                                              const float* A, int lda, int bm,
                                              const float* B, int ldb, int bn,
                                              int tid, int kt) {
    uint32_t sa = sb + s * (STAGEF2 * 4);
    uint32_t sB = sa + A2FLOATS * 4;
    int k0 = kt * 32;
    #pragma unroll
    for (int t = 0; t < 2; t++) {
        int c = tid + t * 512;
        int row = c >> 3, col = c & 7;
        cp16(sa + row * (ASTRIDE*4) + col * 16,
             A + (size_t)(bm + row) * lda + k0 + col * 4);
    }
    #pragma unroll
    for (int t = 0; t < 2; t++) {
        int c = tid + t * 512;
        int row = c >> 5, col = c & 31;
        cp16(sB + row * (BSTRIDE*4) + col * 16,
             B + (size_t)(k0 + row) * ldb + bn + col * 4);
    }
}

__global__ __launch_bounds__(512, 1) void gemm512(const float* __restrict__ A,
                                                  const float* __restrict__ Bw,
                                                  float* __restrict__ C,
                                                  int K, int N, int mode) {
    extern __shared__ float sm[];
    uint32_t sb = smem_u32(sm);
    int tid = threadIdx.x;
    int warp = tid >> 5, lane = tid & 31;
    int wm = (warp & 3) * 32;
    int wn = (warp >> 2) * 32;
    int tg = lane >> 2, tk = lane & 3;
    int bm = blockIdx.y * 128, bn = blockIdx.x * 128;
    int KT = K / 32;

    float acc[2][4][4];
    #pragma unroll
    for (int mt = 0; mt < 2; mt++)
        #pragma unroll
        for (int nt = 0; nt < 4; nt++)
            #pragma unroll
            for (int i = 0; i < 4; i++) acc[mt][nt][i] = 0.f;

    load_stage512(sb, 0, A, K, bm, Bw, N, bn, tid, 0);
    asm volatile("cp.async.commit_group;" ::: "memory");
    load_stage512(sb, 1, A, K, bm, Bw, N, bn, tid, 1);
    asm volatile("cp.async.commit_group;" ::: "memory");

    for (int it = 0; it < KT; it++) {
        asm volatile("cp.async.wait_group 1;" ::: "memory");
        __syncthreads();
        int pf = it + 2;
        if (pf < KT) load_stage512(sb, pf % 3, A, K, bm, Bw, N, bn, tid, pf);
        asm volatile("cp.async.commit_group;" ::: "memory");

        const float* As = sm + (it % 3) * STAGEF2;
        const float* Bs = As + A2FLOATS;
        #pragma unroll
        for (int kq = 0; kq < 32; kq += 8) {
            uint32_t af[2][4], bf[4][2];
            #pragma unroll
            for (int mt = 0; mt < 2; mt++) {
                int m = wm + mt * 16 + tg;
                af[mt][0] = __float_as_uint(As[m * ASTRIDE + kq + tk]);
                af[mt][1] = __float_as_uint(As[(m + 8) * ASTRIDE + kq + tk]);
                af[mt][2] = __float_as_uint(As[m * ASTRIDE + kq + tk + 4]);
                af[mt][3] = __float_as_uint(As[(m + 8) * ASTRIDE + kq + tk + 4]);
            }
            #pragma unroll
            for (int nt = 0; nt < 4; nt++) {
                int n = wn + nt * 8 + tg;
                bf[nt][0] = __float_as_uint(Bs[(kq + tk) * BSTRIDE + n]);
                bf[nt][1] = __float_as_uint(Bs[(kq + tk + 4) * BSTRIDE + n]);
            }
            #pragma unroll
            for (int mt = 0; mt < 2; mt++)
                #pragma unroll
                for (int nt = 0; nt < 4; nt++)
                    mma_tf32(acc[mt][nt], af[mt][0], af[mt][1], af[mt][2], af[mt][3],
                             bf[nt][0], bf[nt][1]);
        }
        __syncthreads();
    }

    #pragma unroll
    for (int mt = 0; mt < 2; mt++) {
        #pragma unroll
        for (int nt = 0; nt < 4; nt++) {
            int r0 = bm + wm + mt * 16 + tg;
            int cc = bn + wn + nt * 8 + tk * 2;
            float2 v0 = make_float2(acc[mt][nt][0], acc[mt][nt][1]);
            float2 v1 = make_float2(acc[mt][nt][2], acc[mt][nt][3]);
            if (mode == 1) {
                v0.x = rnaf(v0.x); v0.y = rnaf(v0.y);
                v1.x = rnaf(v1.x); v1.y = rnaf(v1.y);
            }
            *(float2*)&C[(size_t)r0 * N + cc]       = v0;
            *(float2*)&C[(size_t)(r0 + 8) * N + cc] = v1;
        }
    }
}

// ---------------------------------------------------------------------------
// Fused av (64x128 tiles): e = exp(sim/5) computed on FMA pipe under MMA.
// Unsplit jobs (qt<8) self-normalize; split jobs write partials + rowsums.
// ---------------------------------------------------------------------------
#define AV_AS     0
#define AV_BS     (64*ASTRIDE)
#define AV_PQ     (AV_BS + 3*32*BSTRIDE)
#define AV_PK     (AV_PQ + 320)
#define AV_RS     (AV_PK + 160)
#define AV_FLOATS (AV_RS + 64)
#define SMEM_AV   (AV_FLOATS*4)

__global__ __launch_bounds__(256) void av_fused(const float* __restrict__ paths,
                                                const float* __restrict__ v,
                                                float* __restrict__ ctx,
                                                float* __restrict__ ctx2,
                                                float* __restrict__ rs) {
    extern __shared__ float sm[];
    uint32_t sb = smem_u32(sm);
    int j = blockIdx.x, bh = blockIdx.y;
    int qt = c_qt[j], k0t = c_k0[j], KT = c_kt[j], ds = c_ds[j];
    int b = bh >> 3, h = bh & 7;
    int tid = threadIdx.x;
    int warp = tid >> 5, lane = tid & 31;

    const float* pb = paths + (size_t)(b * Tt) * (Hh*DEPTH) + h * DEPTH;
    const float* Bv = v + (size_t)b * Tt * Dd + h * 128;
    float* As  = sm + AV_AS;
    float* pqs = sm + AV_PQ;
    float* pks = sm + AV_PK;
    float* rsm = sm + AV_RS;

    for (int idx = tid; idx < 64 * DEPTH; idx += 256)
        pqs[idx] = pb[(size_t)(qt * 64 + idx / DEPTH) * (Hh*DEPTH) + idx % DEPTH];

    {
        uint32_t sB = sb + AV_BS * 4;
        #pragma unroll
        for (int s = 0; s < 2; s++) {
            int kb = (k0t + s) * 32;
            #pragma unroll
            for (int t = 0; t < 4; t++) {
                int c = tid + t * 256;
                int row = c >> 5, col = c & 31;
                cp16(sB + s * (32*BSTRIDE*4) + row * (BSTRIDE*4) + col * 16,
                     Bv + (size_t)(kb + row) * Dd + col * 4);
            }
            asm volatile("cp.async.commit_group;" ::: "memory");
        }
    }

    int wm = (warp & 1) * 32;
    int wn = (warp >> 1) * 32;
    int tg = lane >> 2, tk = lane & 3;
    float acc[2][4][4];
    #pragma unroll
    for (int mt = 0; mt < 2; mt++)
        #pragma unroll
        for (int nt = 0; nt < 4; nt++)
            #pragma unroll
            for (int i = 0; i < 4; i++) acc[mt][nt][i] = 0.f;
    float rsum[8];
    #pragma unroll
    for (int i = 0; i < 8; i++) rsum[i] = 0.f;

    for (int it = 0; it < KT; it++) {
        int kb = (k0t + it) * 32;
        if (tid < 32 * DEPTH)
            pks[tid] = pb[(size_t)(kb + tid / DEPTH) * (Hh*DEPTH) + tid % DEPTH];
        __syncthreads();

        {
            float k0v = pks[lane*5+0], k1v = pks[lane*5+1], k2v = pks[lane*5+2],
                  k3v = pks[lane*5+3], k4v = pks[lane*5+4];
            float m0 = 1.f - k0v, m1 = 1.f - k1v, m2 = 1.f - k2v,
                  m3 = 1.f - k3v, m4 = 1.f - k4v;
            int kglob = kb + lane;
            #pragma unroll
            for (int jr = 0; jr < 8; jr++) {
                int row = warp * 8 + jr;
                const float* pq = pqs + row * 5;
                float p0 = pq[0], p1 = pq[1], p2 = pq[2], p3 = pq[3], p4 = pq[4];
                float prod = p0 * k0v + (1.f - p0) * m0;
                float s = prod;
                prod *= p1 * k1v + (1.f - p1) * m1; s += prod;
                prod *= p2 * k2v + (1.f - p2) * m2; s += prod;
                prod *= p3 * k3v + (1.f - p3) * m3; s += prod;
                prod *= p4 * k4v + (1.f - p4) * m4; s += prod;
                float ev = 0.f;
                if (kglob <= qt * 64 + row) ev = rnaf(expap(s * 0.2f));
                rsum[jr] += ev;
                As[row * ASTRIDE + lane] = ev;
            }
        }

        asm volatile("cp.async.wait_group 1;" ::: "memory");
        __syncthreads();

        int pf = it + 2;
        if (pf < KT) {
            uint32_t sB = sb + AV_BS * 4 + (pf % 3) * (32*BSTRIDE*4);
            int kb2 = (k0t + pf) * 32;
            #pragma unroll
            for (int t = 0; t < 4; t++) {
                int c = tid + t * 256;
                int row = c >> 5, col = c & 31;
                cp16(sB + row * (BSTRIDE*4) + col * 16,
                     Bv + (size_t)(kb2 + row) * Dd + col * 4);
            }
        }
        asm volatile("cp.async.commit_group;" ::: "memory");

        const float* Bs = sm + AV_BS + (it % 3) * (32*BSTRIDE);
        #pragma unroll
        for (int kq = 0; kq < 32; kq += 8) {
            uint32_t af[2][4], bf[4][2];
            #pragma unroll
            for (int mt = 0; mt < 2; mt++) {
                int m = wm + mt * 16 + tg;
                af[mt][0] = __float_as_uint(As[m * ASTRIDE + kq + tk]);
                af[mt][1] = __float_as_uint(As[(m + 8) * ASTRIDE + kq + tk]);
                af[mt][2] = __float_as_uint(As[m * ASTRIDE + kq + tk + 4]);
                af[mt][3] = __float_as_uint(As[(m + 8) * ASTRIDE + kq + tk + 4]);
            }
            #pragma unroll
            for (int nt = 0; nt < 4; nt++) {
                int n = wn + nt * 8 + tg;
                bf[nt][0] = __float_as_uint(Bs[(kq + tk) * BSTRIDE + n]);
                bf[nt][1] = __float_as_uint(Bs[(kq + tk + 4) * BSTRIDE + n]);
            }
            #pragma unroll
            for (int mt = 0; mt < 2; mt++)
                #pragma unroll
                for (int nt = 0; nt < 4; nt++)
                    mma_tf32(acc[mt][nt], af[mt][0], af[mt][1], af[mt][2], af[mt][3],
                             bf[nt][0], bf[nt][1]);
        }
    }

    #pragma unroll
    for (int jr = 0; jr < 8; jr++) {
        float s = rsum[jr];
        #pragma unroll
        for (int o = 16; o > 0; o >>= 1) s += __shfl_xor_sync(0xffffffffu, s, o);
        if (lane == 0) rsm[warp * 8 + jr] = s;
    }
    __syncthreads();

    if (qt < 8) {
        float* C = ctx + (size_t)b * Tt * Dd + h * 128;
        #pragma unroll
        for (int mt = 0; mt < 2; mt++) {
            int rl0 = wm + mt * 16 + tg;
            float i0 = 1.f / rsm[rl0], i1 = 1.f / rsm[rl0 + 8];
            #pragma unroll
            for (int nt = 0; nt < 4; nt++) {
                int r0 = qt * 64 + rl0;
                int cc = wn + nt * 8 + tk * 2;
                *(float2*)&C[(size_t)r0 * Dd + cc] =
                    make_float2(rnaf(acc[mt][nt][0] * i0), rnaf(acc[mt][nt][1] * i0));
                *(float2*)&C[(size_t)(r0 + 8) * Dd + cc] =
                    make_float2(rnaf(acc[mt][nt][2] * i1), rnaf(acc[mt][nt][3] * i1));
            }
        }
    } else {
        if (tid < 64) {
            float* rsp = rs + (size_t)ds * (Bb*Hh) * Tt + (size_t)bh * Tt + qt * 64;
            rsp[tid] = rsm[tid];
        }
        float* C = (ds ? ctx2 : ctx) + (size_t)b * Tt * Dd + h * 128;
        #pragma unroll
        for (int mt = 0; mt < 2; mt++) {
            #pragma unroll
            for (int nt = 0; nt < 4; nt++) {
                int r0 = qt * 64 + wm + mt * 16 + tg;
                int cc = wn + nt * 8 + tk * 2;
                *(float2*)&C[(size_t)r0 * Dd + cc]       = make_float2(acc[mt][nt][0], acc[mt][nt][1]);
                *(float2*)&C[(size_t)(r0 + 8) * Dd + cc] = make_float2(acc[mt][nt][2], acc[mt][nt][3]);
            }
        }
    }
}

// normalize + combine rows t>=512 only
__global__ __launch_bounds__(256) void ctx_norm(float4* __restrict__ ctx,
                                                const float4* __restrict__ ctx2,
                                                const float* __restrict__ rs) {
    int i = blockIdx.x * 256 + threadIdx.x;
    const int per_b = 512 * Dd / 4;
    if (i < Bb * per_b) {
        int b = i / per_b;
        int off = i - b * per_b;
        int t = 512 + off / (Dd / 4);
        int c4 = off % (Dd / 4);
        int bh = b * 8 + (c4 >> 5);
        size_t gi = (size_t)b * Tt * (Dd/4) + (size_t)t * (Dd/4) + c4;
        float denom = rs[(size_t)bh * Tt + t] + rs[(size_t)(Bb*Hh) * Tt + (size_t)bh * Tt + t];
        float inv = 1.f / denom;
        float4 xa = ctx[gi], xb = ctx2[gi];
        ctx[gi] = make_float4(rnaf((xa.x + xb.x) * inv), rnaf((xa.y + xb.y) * inv),
                              rnaf((xa.z + xb.z) * inv), rnaf((xa.w + xb.w) * inv));
    }
}

// ---------------------------------------------------------------------------
// paths GEMM split-K x4 (split-tf32) + sigmoid combine
// ---------------------------------------------------------------------------
#define PSTAGEF (2*64*36 + 2*32*136)
#define SMEM_PATHS (2*PSTAGEF*4)

__device__ __forceinline__ void paths_load(uint32_t sb, int s,
                                           const float* xh, const float* xl, int bm,
                                           const float* wh, const float* wl,
                                           int tid, int kt) {
    uint32_t base = sb + s * (PSTAGEF * 4);
    uint32_t xh_o = base;
    uint32_t xl_o = base + 64*36*4;
    uint32_t wh_o = xl_o + 64*36*4;
    uint32_t wl_o = wh_o + 32*136*4;
    int k0 = kt * 32;
    #pragma unroll
    for (int t = 0; t < 2; t++) {
        int c = tid + t * 256;
        int row = c >> 3, col = c & 7;
        size_t go = (size_t)(bm + row) * Dd + k0 + col * 4;
        uint32_t so = row * (36*4) + col * 16;
        cp16(xh_o + so, xh + go);
        cp16(xl_o + so, xl + go);
    }
    #pragma unroll
    for (int t = 0; t < 4; t++) {
        int c = tid + t * 256;
        int row = c >> 5, col = c & 31;
        size_t go = (size_t)(k0 + row) * 128 + col * 4;
        uint32_t so = row * (136*4) + col * 16;
        cp16(wh_o + so, wh + go);
        cp16(wl_o + so, wl + go);
    }
}

__global__ __launch_bounds__(256) void paths_gemm(const float* __restrict__ xh0,
                                                  const float* __restrict__ xl0,
                                                  const float* __restrict__ wh0,
                                                  const float* __restrict__ wl0,
                                                  float* __restrict__ pp) {
    extern __shared__ float sm[];
    uint32_t sb = smem_u32(sm);
    int tid = threadIdx.x;
    int warp = tid >> 5, lane = tid & 31;
    int wm = (warp & 1) * 32;
    int wn = (warp >> 1) * 32;
    int tg = lane >> 2, tk = lane & 3;
    int bm = blockIdx.x * 64;
    int sp = blockIdx.y;
    const float* xh = xh0 + sp * 256;
    const float* xl = xl0 + sp * 256;
    const float* wh = wh0 + (size_t)(sp * 256) * 128;
    const float* wl = wl0 + (size_t)(sp * 256) * 128;
    float* out = pp + (size_t)sp * NTOK * 128;
    const int KT = 8;

    float acc[2][4][4];
    #pragma unroll
    for (int mt = 0; mt < 2; mt++)
        #pragma unroll
        for (int nt = 0; nt < 4; nt++)
            #pragma unroll
            for (int i = 0; i < 4; i++) acc[mt][nt][i] = 0.f;

    paths_load(sb, 0, xh, xl, bm, wh, wl, tid, 0);
    asm volatile("cp.async.commit_group;" ::: "memory");

    for (int it = 0; it < KT; it++) {
        int pf = it + 1;
        if (pf < KT) {
            paths_load(sb, pf & 1, xh, xl, bm, wh, wl, tid, pf);
            asm volatile("cp.async.commit_group;" ::: "memory");
            asm volatile("cp.async.wait_group 1;" ::: "memory");
        } else {
            asm volatile("cp.async.wait_group 0;" ::: "memory");
        }
        __syncthreads();

        const float* Xh = sm + (it & 1) * PSTAGEF;
        const float* Xl = Xh + 64*36;
        const float* Wh = Xl + 64*36;
        const float* Wl = Wh + 32*136;
        #pragma unroll
        for (int kq = 0; kq < 32; kq += 8) {
            uint32_t ah[2][4], al[2][4], bh[4][2], bl[4][2];
            #pragma unroll
            for (int mt = 0; mt < 2; mt++) {
                int m = wm + mt * 16 + tg;
                ah[mt][0] = __float_as_uint(Xh[m * 36 + kq + tk]);
                ah[mt][1] = __float_as_uint(Xh[(m + 8) * 36 + kq + tk]);
                ah[mt][2] = __float_as_uint(Xh[m * 36 + kq + tk + 4]);
                ah[mt][3] = __float_as_uint(Xh[(m + 8) * 36 + kq + tk + 4]);
                al[mt][0] = __float_as_uint(Xl[m * 36 + kq + tk]);
                al[mt][1] = __float_as_uint(Xl[(m + 8) * 36 + kq + tk]);
                al[mt][2] = __float_as_uint(Xl[m * 36 + kq + tk + 4]);
                al[mt][3] = __float_as_uint(Xl[(m + 8) * 36 + kq + tk + 4]);
            }
            #pragma unroll
            for (int nt = 0; nt < 4; nt++) {
                int n = wn + nt * 8 + tg;
                bh[nt][0] = __float_as_uint(Wh[(kq + tk) * 136 + n]);
                bh[nt][1] = __float_as_uint(Wh[(kq + tk + 4) * 136 + n]);
                bl[nt][0] = __float_as_uint(Wl[(kq + tk) * 136 + n]);
                bl[nt][1] = __float_as_uint(Wl[(kq + tk + 4) * 136 + n]);
            }
            #pragma unroll
            for (int mt = 0; mt < 2; mt++)
                #pragma unroll
                for (int nt = 0; nt < 4; nt++) {
                    mma_tf32(acc[mt][nt], ah[mt][0], ah[mt][1], ah[mt][2], ah[mt][3],
                             bh[nt][0], bh[nt][1]);
                    mma_tf32(acc[mt][nt], ah[mt][0], ah[mt][1], ah[mt][2], ah[mt][3],
                             bl[nt][0], bl[nt][1]);
                    mma_tf32(acc[mt][nt], al[mt][0], al[mt][1], al[mt][2], al[mt][3],
                             bh[nt][0], bh[nt][1]);
                }
        }
        __syncthreads();
    }

    #pragma unroll
    for (int mt = 0; mt < 2; mt++) {
        #pragma unroll
        for (int nt = 0; nt < 4; nt++) {
            int cc = wn + nt * 8 + tk * 2;
            if (cc < Hh * DEPTH) {
                int r0 = bm + wm + mt * 16 + tg;
                out[(size_t)r0 * 128 + cc]           = acc[mt][nt][0];
                out[(size_t)r0 * 128 + cc + 1]       = acc[mt][nt][1];
                out[(size_t)(r0 + 8) * 128 + cc]     = acc[mt][nt][2];
                out[(size_t)(r0 + 8) * 128 + cc + 1] = acc[mt][nt][3];
            }
        }
    }
}

__global__ __launch_bounds__(256) void sigmoid_comb(const float* __restrict__ pp,
                                                    const float* __restrict__ bp,
                                                    float* __restrict__ paths) {
    int tok = blockIdx.x * 4 + (threadIdx.x >> 6);
    int c = threadIdx.x & 63;
    if (c < Hh * DEPTH) {
        float z = bp[c];
        #pragma unroll
        for (int s = 0; s < 4; s++)
            z += pp[(size_t)s * NTOK * 128 + (size_t)tok * 128 + c];
        paths[(size_t)tok * (Hh*DEPTH) + c] = 1.f / (1.f + expf(-z));
    }
}

// ---------------- merged staging ----------------
__global__ __launch_bounds__(256) void prep_all(const float4* __restrict__ x,
                                                float4* __restrict__ xh,
                                                float4* __restrict__ xl,
                                                const float4* __restrict__ Wv,
                                                float4* __restrict__ wvr,
                                                const float4* __restrict__ Wo,
                                                float4* __restrict__ wor,
                                                const float* __restrict__ Wp) {
    int i = blockIdx.x * 256 + threadIdx.x;
    if (i < NTOK*Dd/4) {
        float4 v = x[i];
        float4 h = make_float4(rnaf(v.x), rnaf(v.y), rnaf(v.z), rnaf(v.w));
        xh[i] = h;
        xl[i] = make_float4(rnaf(v.x - h.x), rnaf(v.y - h.y), rnaf(v.z - h.z), rnaf(v.w - h.w));
    }
    if (i < Dd*Dd/4) {
        float4 a = Wv[i], b = Wo[i];
        wvr[i] = make_float4(rnaf(a.x), rnaf(a.y), rnaf(a.z), rnaf(a.w));
        wor[i] = make_float4(rnaf(b.x), rnaf(b.y), rnaf(b.z), rnaf(b.w));
    }
    if (i < Dd*128) {
        int k = i >> 7, n = i & 127;
        float h = 0.f, l = 0.f;
        if (n < Hh * DEPTH) {
            float w = Wp[(size_t)k * (Hh * DEPTH) + n];
            h = rnaf(w);
            l = rnaf(w - h);
        }
        g_wph[i] = h;
        g_wpl[i] = l;
    }
}

// ---------------------------------------------------------------------------
extern "C" void kernel_launch(void* const* d_in, const int* in_sizes, int n_in,
                              void* d_out, int out_size) {
    const float* x  = (const float*)d_in[0];
    const float* Wp = (const float*)d_in[1];
    const float* bp = (const float*)d_in[2];
    const float* Wv = (const float*)d_in[3];
    const float* Wo = (const float*)d_in[4];
    float* out = (float*)d_out;

    float *paths, *xr, *xlo, *wph, *wpl, *pp, *wvr, *wor, *v, *ctx, *ctx2, *rs;
    cudaGetSymbolAddress((void**)&paths, g_paths);
    cudaGetSymbolAddress((void**)&xr,    g_xr);
    cudaGetSymbolAddress((void**)&xlo,   g_xlo);
    cudaGetSymbolAddress((void**)&wph,   g_wph);
    cudaGetSymbolAddress((void**)&wpl,   g_wpl);
    cudaGetSymbolAddress((void**)&pp,    g_pp);
    cudaGetSymbolAddress((void**)&wvr,   g_wvr);
    cudaGetSymbolAddress((void**)&wor,   g_wor);
    cudaGetSymbolAddress((void**)&v,     g_v);
    cudaGetSymbolAddress((void**)&ctx,   g_ctx);
    cudaGetSymbolAddress((void**)&ctx2,  g_ctx2);
    cudaGetSymbolAddress((void**)&rs,    g_rs);

    cudaFuncSetAttribute(gemm512,    cudaFuncAttributeMaxDynamicSharedMemorySize, SMEM_GEMM2);
    cudaFuncSetAttribute(av_fused,   cudaFuncAttributeMaxDynamicSharedMemorySize, SMEM_AV);
    cudaFuncSetAttribute(paths_gemm, cudaFuncAttributeMaxDynamicSharedMemorySize, SMEM_PATHS);

    // merged staging
    prep_all<<<(NTOK*Dd/4 + 255)/256, 256>>>((const float4*)x, (float4*)xr, (float4*)xlo,
                                             (const float4*)Wv, (float4*)wvr,
                                             (const float4*)Wo, (float4*)wor, Wp);

    // paths = sigmoid(x @ Wp + bp)
    paths_gemm<<<dim3(NTOK/64, 4), 256, SMEM_PATHS>>>(xr, xlo, wph, wpl, pp);
    sigmoid_comb<<<NTOK/4, 256>>>(pp, bp, paths);

    // V = x @ Wv (rounded store)
    gemm512<<<dim3(Dd/128, NTOK/128), 512, SMEM_GEMM2>>>(xr, wvr, v, Dd, Dd, 1);

    // fused sim+softmax+attn@V
    av_fused<<<dim3(24, Bb*Hh), 256, SMEM_AV>>>(paths, v, ctx, ctx2, rs);

    // combine split rows (t >= 512)
    ctx_norm<<<(Bb*512*Dd/4 + 255)/256, 256>>>((float4*)ctx, (const float4*)ctx2, rs);

    // out = ctx @ Wo
    gemm512<<<dim3(Dd/128, NTOK/128), 512, SMEM_GEMM2>>>(ctx, wor, out, Dd, Dd, 0);
}